// round 1
// baseline (speedup 1.0000x reference)
#include <cuda_runtime.h>
#include <cstdint>

// Problem constants (fixed shapes from the reference)
#define B        2
#define N_PRE    50000
#define N_POST   50000
#define N_SYN    10000000
#define N_TYPES  20
#define N_BASIS  5

__global__ void zero_kernel(float* __restrict__ out, int n) {
    int i = blockIdx.x * blockDim.x + threadIdx.x;
    if (i < n) out[i] = 0.0f;
}

__global__ __launch_bounds__(256)
void accum_kernel(const float* __restrict__ spikes,        // [B, N_PRE]
                  const float* __restrict__ weights,       // [N_SYN]
                  const float* __restrict__ basis,         // [N_TYPES, N_BASIS]
                  const int2*  __restrict__ syn_idx,       // [N_SYN] (post, pre)
                  const int*   __restrict__ syn_ids,       // [N_SYN]
                  float*       __restrict__ out)           // [B*N_POST, N_BASIS]
{
    __shared__ float sb[N_TYPES * N_BASIS];
    if (threadIdx.x < N_TYPES * N_BASIS) sb[threadIdx.x] = basis[threadIdx.x];
    __syncthreads();

    int i = blockIdx.x * blockDim.x + threadIdx.x;
    if (i >= N_SYN) return;

    int2 pi  = syn_idx[i];
    int post = pi.x;
    int pre  = pi.y;

    // Spike gather — tiny buffer, stays resident in L2/L1.
    float s0 = __ldg(spikes + pre);
    float s1 = __ldg(spikes + N_PRE + pre);
    if (s0 == 0.0f && s1 == 0.0f) return;   // ~96% of threads exit here

    // Only touch weight/type streams if something fired in this lane —
    // skips ~27% of those cache lines chip-wide.
    float wv = __ldg(weights + i);
    int   t  = __ldg(syn_ids + i);

    const float* bt = sb + t * N_BASIS;
    float c0 = wv * bt[0];
    float c1 = wv * bt[1];
    float c2 = wv * bt[2];
    float c3 = wv * bt[3];
    float c4 = wv * bt[4];

    if (s0 != 0.0f) {
        float* o = out + (size_t)post * N_BASIS;
        atomicAdd(o + 0, c0);
        atomicAdd(o + 1, c1);
        atomicAdd(o + 2, c2);
        atomicAdd(o + 3, c3);
        atomicAdd(o + 4, c4);
    }
    if (s1 != 0.0f) {
        float* o = out + ((size_t)N_POST + (size_t)post) * N_BASIS;
        atomicAdd(o + 0, c0);
        atomicAdd(o + 1, c1);
        atomicAdd(o + 2, c2);
        atomicAdd(o + 3, c3);
        atomicAdd(o + 4, c4);
    }
}

extern "C" void kernel_launch(void* const* d_in, const int* in_sizes, int n_in,
                              void* d_out, int out_size)
{
    const float* spikes  = (const float*)d_in[0];   // rec_z_buf [B, N_PRE]
    const float* weights = (const float*)d_in[1];   // weight_values [N_SYN]
    const float* basis   = (const float*)d_in[2];   // synaptic_basis_weights [20,5]
    const int2*  syn_idx = (const int2*)d_in[3];    // synapse_indices [N_SYN,2]
    const int*   syn_ids = (const int*)d_in[4];     // syn_ids [N_SYN]
    float* out = (float*)d_out;                     // [B*N_POST, N_BASIS]

    // Zero the poisoned output buffer.
    {
        int threads = 256;
        int blocks  = (out_size + threads - 1) / threads;
        zero_kernel<<<blocks, threads>>>(out, out_size);
    }

    // Scatter-accumulate over all synapses.
    {
        int threads = 256;
        int blocks  = (N_SYN + threads - 1) / threads;
        accum_kernel<<<blocks, threads>>>(spikes, weights, basis, syn_idx, syn_ids, out);
    }
}

// round 2
// speedup vs baseline: 2.1836x; 2.1836x over previous
#include <cuda_runtime.h>
#include <cstdint>

#define B        2
#define N_PRE    50000
#define N_POST   50000
#define N_SYN    10000000
#define N_TYPES  20
#define N_BASIS  5

#define MASK_WORDS ((N_PRE + 15) / 16)   // 2 bits per neuron -> 3125 words

__device__ uint32_t g_spike_mask[MASK_WORDS];

// Zero the poisoned output.
__global__ void zero_kernel(float* __restrict__ out, int n) {
    int i = blockIdx.x * blockDim.x + threadIdx.x;
    if (i < n) out[i] = 0.0f;
}

// Build packed spike mask: word w covers neurons [16w, 16w+16),
// 2 bits each: bit0 = batch0 fired, bit1 = batch1 fired.
__global__ void mask_kernel(const float* __restrict__ spikes) {
    int w = blockIdx.x * blockDim.x + threadIdx.x;
    if (w >= MASK_WORDS) return;
    uint32_t m = 0;
    int base = w * 16;
    #pragma unroll
    for (int j = 0; j < 16; j++) {
        int pre = base + j;
        if (pre < N_PRE) {
            uint32_t b0 = (spikes[pre] != 0.0f) ? 1u : 0u;
            uint32_t b1 = (spikes[N_PRE + pre] != 0.0f) ? 1u : 0u;
            m |= (b0 | (b1 << 1)) << (j * 2);
        }
    }
    g_spike_mask[w] = m;
}

__global__ __launch_bounds__(256)
void accum_kernel(const float* __restrict__ weights,       // [N_SYN]
                  const float* __restrict__ basis,         // [N_TYPES, N_BASIS]
                  const int4*  __restrict__ syn_idx4,      // [N_SYN/2] pairs of (post,pre)
                  const int*   __restrict__ syn_ids,       // [N_SYN]
                  float*       __restrict__ out)           // [B*N_POST, N_BASIS]
{
    __shared__ uint32_t smask[MASK_WORDS];
    __shared__ float sb[N_TYPES * N_BASIS];

    for (int i = threadIdx.x; i < MASK_WORDS; i += blockDim.x)
        smask[i] = g_spike_mask[i];
    if (threadIdx.x < N_TYPES * N_BASIS) sb[threadIdx.x] = basis[threadIdx.x];
    __syncthreads();

    const int NV = N_SYN / 2;   // int4 elements
    int stride = gridDim.x * blockDim.x;

    for (int i = blockIdx.x * blockDim.x + threadIdx.x; i < NV; i += stride) {
        int4 v = syn_idx4[i];
        // synapse a = 2i: post=v.x pre=v.y ; synapse b = 2i+1: post=v.z pre=v.w
        uint32_t wa = smask[v.y >> 4];
        uint32_t wb = smask[v.w >> 4];
        uint32_t ba = (wa >> ((v.y & 15) << 1)) & 3u;
        uint32_t bb = (wb >> ((v.w & 15) << 1)) & 3u;

        if ((ba | bb) == 0u) continue;   // ~92% skip

        int s = i * 2;
        // Adjacent pair: load both weights/ids in one shot (same sectors).
        float2 wv = __ldg((const float2*)(weights + s));
        int2   tt = __ldg((const int2*)(syn_ids + s));

        if (ba) {
            const float* bt = sb + tt.x * N_BASIS;
            float c0 = wv.x * bt[0], c1 = wv.x * bt[1], c2 = wv.x * bt[2],
                  c3 = wv.x * bt[3], c4 = wv.x * bt[4];
            if (ba & 1u) {
                float* o = out + (size_t)v.x * N_BASIS;
                atomicAdd(o + 0, c0); atomicAdd(o + 1, c1); atomicAdd(o + 2, c2);
                atomicAdd(o + 3, c3); atomicAdd(o + 4, c4);
            }
            if (ba & 2u) {
                float* o = out + ((size_t)N_POST + v.x) * N_BASIS;
                atomicAdd(o + 0, c0); atomicAdd(o + 1, c1); atomicAdd(o + 2, c2);
                atomicAdd(o + 3, c3); atomicAdd(o + 4, c4);
            }
        }
        if (bb) {
            const float* bt = sb + tt.y * N_BASIS;
            float c0 = wv.y * bt[0], c1 = wv.y * bt[1], c2 = wv.y * bt[2],
                  c3 = wv.y * bt[3], c4 = wv.y * bt[4];
            if (bb & 1u) {
                float* o = out + (size_t)v.z * N_BASIS;
                atomicAdd(o + 0, c0); atomicAdd(o + 1, c1); atomicAdd(o + 2, c2);
                atomicAdd(o + 3, c3); atomicAdd(o + 4, c4);
            }
            if (bb & 2u) {
                float* o = out + ((size_t)N_POST + v.z) * N_BASIS;
                atomicAdd(o + 0, c0); atomicAdd(o + 1, c1); atomicAdd(o + 2, c2);
                atomicAdd(o + 3, c3); atomicAdd(o + 4, c4);
            }
        }
    }
}

extern "C" void kernel_launch(void* const* d_in, const int* in_sizes, int n_in,
                              void* d_out, int out_size)
{
    const float* spikes  = (const float*)d_in[0];   // rec_z_buf [B, N_PRE]
    const float* weights = (const float*)d_in[1];   // weight_values [N_SYN]
    const float* basis   = (const float*)d_in[2];   // synaptic_basis_weights [20,5]
    const int4*  syn_idx = (const int4*)d_in[3];    // synapse_indices [N_SYN,2] as pairs
    const int*   syn_ids = (const int*)d_in[4];     // syn_ids [N_SYN]
    float* out = (float*)d_out;                     // [B*N_POST, N_BASIS]

    {
        int threads = 256;
        int blocks  = (out_size + threads - 1) / threads;
        zero_kernel<<<blocks, threads>>>(out, out_size);
    }
    {
        int threads = 256;
        int blocks  = (MASK_WORDS + threads - 1) / threads;
        mask_kernel<<<blocks, threads>>>(spikes);
    }
    {
        int threads = 256;
        int blocks  = 1184;   // 8 blocks/SM * 148 SMs: single persistent wave
        accum_kernel<<<blocks, threads>>>(weights, basis, syn_idx, syn_ids, out);
    }
}